// round 14
// baseline (speedup 1.0000x reference)
#include <cuda_runtime.h>

#define T_STEPS 16384
#define H 361

#define CSZ 12             /* cluster CTAs == sources == segments */
#define RPC 32             /* rows per CTA (lane l <-> row rank*32+l) */
#define SEGC 32            /* columns per segment */
#define HB 384             /* h buffer floats */
#define NTHR 384           /* 12 warps: warp s consumes source s */
#define TXB 128            /* 32 lanes x 4B per (source, consumer, step) */
#define PST2 66            /* packed psum pair-row stride (floats) */

#define KAPPA_F 32.84045313f
#define NORMF   2.2773755f
#define DEG2RAD 0.017453292519943295f
#define SC2LOG2E 2.885390081777927f   /* 2*log2(e): pre-scale so sum feeds ex2 */

// ---------------- device scratch ----------------
__device__ float g_xw[T_STEPS * H];     // stores 2*log2(e) * xw
__device__ float g_W2T[H * 368];
__device__ float g_A[H];
__device__ float g_C[H];
__device__ float g_hs[T_STEPS * H];     // fallback hs store

__device__ __forceinline__ unsigned smem_u32(const void* p) {
    return (unsigned)__cvta_generic_to_shared(p);
}
__device__ __forceinline__ unsigned mapa_u32(unsigned addr, unsigned rank) {
    unsigned r;
    asm("mapa.shared::cluster.u32 %0, %1, %2;" : "=r"(r) : "r"(addr), "r"(rank));
    return r;
}

// ---------------- K0: collapse rule projection + biases ----------------
__global__ void k0_prep(const float* __restrict__ w_rule, const float* __restrict__ b_rule,
                        const float* __restrict__ w_ih, const float* __restrict__ b_ih,
                        const float* __restrict__ b_hh) {
    int j = blockIdx.x * blockDim.x + threadIdx.x;
    if (j >= H) return;
    float a = 0.f, c = 0.f;
    const float* wr = w_ih + j * 489;
    for (int k = 0; k < 128; k++) {
        float w = wr[k];
        a = fmaf(w_rule[k], w, a);
        c = fmaf(b_rule[k], w, c);
    }
    g_A[j] = a;
    g_C[j] = c + b_ih[j] + b_hh[j];
}

__global__ void k0_transpose(const float* __restrict__ w_ih) {
    int idx = blockIdx.x * blockDim.x + threadIdx.x;
    if (idx >= H * H) return;
    int j = idx / H;
    int g = idx - j * H;
    g_W2T[g * 368 + j] = w_ih[j * 489 + 128 + g];
}

// ---------------- K1: xw precompute (output pre-scaled by 2*log2e) ----------------
#define TT 16
__global__ __launch_bounds__(384) void k1_xw(const float* __restrict__ angle,
                                             const float* __restrict__ rule) {
    __shared__ float sE[TT][H];
    __shared__ float sAng[TT], sRule[TT];
    int tid = threadIdx.x;
    int t0 = blockIdx.x * TT;
    if (tid < TT) {
        sAng[tid]  = angle[t0 + tid] * DEG2RAD;
        sRule[tid] = rule[t0 + tid];
    }
    __syncthreads();
    if (tid < H) {
        float gr = (float)tid * DEG2RAD;
        #pragma unroll
        for (int tt = 0; tt < TT; tt++) {
            float th = gr - sAng[tt];
            sE[tt][tid] = __expf(KAPPA_F * (cosf(th) - 1.0f)) * NORMF;
        }
    }
    __syncthreads();
    if (tid < H) {
        float acc[TT];
        #pragma unroll
        for (int tt = 0; tt < TT; tt++) acc[tt] = 0.f;
        #pragma unroll 2
        for (int g = 0; g < H; g++) {
            float w = g_W2T[g * 368 + tid];
            #pragma unroll
            for (int tt = 0; tt < TT; tt++) acc[tt] = fmaf(sE[tt][g], w, acc[tt]);
        }
        float aj = g_A[tid], cj = g_C[tid];
        #pragma unroll
        for (int tt = 0; tt < TT; tt++)
            g_xw[(t0 + tt) * H + tid] = (acc[tt] + fmaf(sRule[tt], aj, cj)) * SC2LOG2E;
    }
}

// ---------------- K2: warp-per-source RNN, 12-CTA cluster ----------------
// R14 vs R12: post-BAR sum+tanh computed ONLY by warps 0-3 (one per SMSP),
// each sending to 3 dests {w, w+4, w+8} — removes the 3x redundant-issue
// penalty per SMSP. psum exchanged as packed f32 pairs (6 u64 loads). hs
// written directly to the output buffer.
__global__ void __launch_bounds__(NTHR, 1)
k2_rnn(const float* __restrict__ w_hh, float* __restrict__ hs_out) {
    __shared__ __align__(16) float hbuf0[HB];
    __shared__ __align__(16) float hbuf1[HB];
    __shared__ __align__(8) float psum[6 * PST2];   // pair p=(s>>1): [p*PST2 + 2*lane + (s&1)]
    __shared__ __align__(8) unsigned long long mbar[2][CSZ];

    int tid  = threadIdx.x;
    int lane = tid & 31;
    int s    = tid >> 5;          // warp id == source id
    unsigned rank;
    asm("mov.u32 %0, %%cluster_ctarank;" : "=r"(rank));
    int grow = (int)rank * RPC + lane;   // the row this lane serves
    bool rowok = (grow < H);

    for (int i = tid; i < HB; i += NTHR) { hbuf0[i] = 0.f; hbuf1[i] = 0.f; }
    if (tid == 0) {
        for (int b = 0; b < 2; b++)
            for (int k = 0; k < CSZ; k++) {
                unsigned mb = smem_u32(&mbar[b][k]);
                asm volatile("mbarrier.init.shared.b64 [%0], 1;" :: "r"(mb) : "memory");
                asm volatile("mbarrier.arrive.expect_tx.shared.b64 _, [%0], %1;"
                             :: "r"(mb), "r"((unsigned)TXB) : "memory");
            }
    }

    // weights: lane l of warp s holds 2log2e * W[grow, 32s..32s+32) as 16 f32x2
    unsigned long long wp[SEGC / 2];
    #pragma unroll
    for (int i = 0; i < SEGC / 2; i++) {
        int c0 = s * SEGC + 2 * i;
        int c1 = c0 + 1;
        float a = (rowok && c0 < H) ? w_hh[grow * H + c0] * SC2LOG2E : 0.f;
        float b = (rowok && c1 < H) ? w_hh[grow * H + c1] * SC2LOG2E : 0.f;
        asm("mov.b64 %0, {%1, %2};" : "=l"(wp[i]) : "f"(a), "f"(b));
    }

    unsigned mbA = smem_u32(&mbar[0][s]);   // my wait barriers (source s)
    unsigned mbB = smem_u32(&mbar[1][s]);

    // sender endpoints: warp w (w<4) sends this CTA's 32 h values to CTAs
    // {w, w+4, w+8}, signaling their mbar[.][rank]
    unsigned sd0[3], sd1[3], sm0[3], sm1[3];
    if (s < 4) {
        unsigned off = (unsigned)(rank * RPC + lane) * 4u;
        unsigned b0 = smem_u32(hbuf0) + off;
        unsigned b1 = smem_u32(hbuf1) + off;
        unsigned m0 = smem_u32(&mbar[0][rank]);
        unsigned m1 = smem_u32(&mbar[1][rank]);
        #pragma unroll
        for (int j = 0; j < 3; j++) {
            unsigned dc = (unsigned)(s + 4 * j);
            sd0[j] = mapa_u32(b0, dc);
            sd1[j] = mapa_u32(b1, dc);
            sm0[j] = mapa_u32(m0, dc);
            sm1[j] = mapa_u32(m1, dc);
        }
    }
    // hoisted per-parity dot pointers (segment s of each buffer)
    const double2* h2_0 = reinterpret_cast<const double2*>(hbuf0 + s * SEGC);
    const double2* h2_1 = reinterpret_cast<const double2*>(hbuf1 + s * SEGC);
    // packed psum write address: pair (s>>1), half (s&1)
    float* pw = &psum[(s >> 1) * PST2 + 2 * lane + (s & 1)];

    float xw_cur = (s == 0 && rowok) ? g_xw[grow] : 0.f;
    unsigned pA = 0, pB = 0;

    __syncthreads();
    asm volatile("barrier.cluster.arrive.aligned;" ::: "memory");
    asm volatile("barrier.cluster.wait.aligned;" ::: "memory");

    for (int t = 0; t < T_STEPS; t++) {
        const double2* h2 = (t & 1) ? h2_1 : h2_0;
        unsigned mb = (t & 1) ? mbB : mbA;

        if (t) {
            unsigned par = (t & 1) ? pB : pA;
            // all lanes wait (warp-synchronous poll)
            asm volatile(
                "{\n\t.reg .pred P1;\n\t"
                "WAITLP_%=:\n\t"
                "mbarrier.try_wait.parity.acquire.cluster.shared::cta.b64 P1, [%0], %1, 0x989680;\n\t"
                "@!P1 bra WAITLP_%=;\n\t}"
                :: "r"(mb), "r"(par) : "memory");
            if (t & 1) pB ^= 1; else pA ^= 1;
        }

        // segment dot: 8 broadcast 16B LDS + 16 f32x2 FMAs (2 chains)
        unsigned long long a01 = 0ull, a23 = 0ull;
        #pragma unroll
        for (int i = 0; i < 8; i++) {
            double2 hv = h2[i];
            unsigned long long hlo = __double_as_longlong(hv.x);
            unsigned long long hhi = __double_as_longlong(hv.y);
            asm("fma.rn.f32x2 %0, %1, %2, %0;" : "+l"(a01) : "l"(wp[2 * i]),     "l"(hlo));
            asm("fma.rn.f32x2 %0, %1, %2, %0;" : "+l"(a23) : "l"(wp[2 * i + 1]), "l"(hhi));
        }
        unsigned long long ssum;
        asm("add.rn.f32x2 %0, %1, %2;" : "=l"(ssum) : "l"(a01), "l"(a23));
        unsigned alo, ahi;
        asm("mov.b64 {%0, %1}, %2;" : "=r"(alo), "=r"(ahi) : "l"(ssum));
        float part = __uint_as_float(alo) + __uint_as_float(ahi);
        if (s == 0) part += xw_cur;            // fold (pre-scaled) input drive
        *pw = part;

        // prefetch next xw while others finish (warp 0 only)
        float xw_nxt = 0.f;
        if (s == 0 && rowok && (t + 1 < T_STEPS)) xw_nxt = __ldg(&g_xw[(t + 1) * H + grow]);

        __syncthreads();   // all 12 partials staged; also fences buf reads

        if (s < 4) {
            // packed sum: 6 u64 loads + f32x2 tree
            const unsigned long long* pp =
                reinterpret_cast<const unsigned long long*>(&psum[2 * lane]);
            unsigned long long u0 = pp[0];
            unsigned long long u1 = pp[PST2 / 2];
            unsigned long long u2 = pp[2 * (PST2 / 2)];
            unsigned long long u3 = pp[3 * (PST2 / 2)];
            unsigned long long u4 = pp[4 * (PST2 / 2)];
            unsigned long long u5 = pp[5 * (PST2 / 2)];
            unsigned long long q0, q1, q2, q3, qs;
            asm("add.rn.f32x2 %0, %1, %2;" : "=l"(q0) : "l"(u0), "l"(u1));
            asm("add.rn.f32x2 %0, %1, %2;" : "=l"(q1) : "l"(u2), "l"(u3));
            asm("add.rn.f32x2 %0, %1, %2;" : "=l"(q2) : "l"(u4), "l"(u5));
            asm("add.rn.f32x2 %0, %1, %2;" : "=l"(q3) : "l"(q0), "l"(q1));
            asm("add.rn.f32x2 %0, %1, %2;" : "=l"(qs) : "l"(q3), "l"(q2));
            unsigned vlo, vhi;
            asm("mov.b64 {%0, %1}, %2;" : "=r"(vlo), "=r"(vhi) : "l"(qs));
            float v = __uint_as_float(vlo) + __uint_as_float(vhi);  // 2log2e*(Wh+xw)

            float e;
            asm("ex2.approx.f32 %0, %1;" : "=f"(e) : "f"(v));   // e^{2x}
            float hval = 1.0f - __fdividef(2.0f, e + 1.0f);     // tanh(x); pads -> 0

            if (t + 1 < T_STEPS) {
                unsigned r_ = __float_as_uint(hval);
                if (t & 1) {
                    #pragma unroll
                    for (int j = 0; j < 3; j++)
                        asm volatile(
                            "st.async.shared::cluster.mbarrier::complete_tx::bytes.u32 [%0], %1, [%2];"
                            :: "r"(sd0[j]), "r"(r_), "r"(sm0[j]) : "memory");
                } else {
                    #pragma unroll
                    for (int j = 0; j < 3; j++)
                        asm volatile(
                            "st.async.shared::cluster.mbarrier::complete_tx::bytes.u32 [%0], %1, [%2];"
                            :: "r"(sd1[j]), "r"(r_), "r"(sm1[j]) : "memory");
                }
            }
            if (s == 0 && rowok) hs_out[t * H + grow] = hval;   // coalesced STG
        }

        // re-arm the barrier consumed this step, for step t+2 (off critical path)
        if (t && lane == 0) {
            asm volatile("mbarrier.arrive.expect_tx.shared.b64 _, [%0], %1;"
                         :: "r"(mb), "r"((unsigned)TXB) : "memory");
        }
        xw_cur = xw_nxt;
    }
    asm volatile("barrier.cluster.arrive.aligned;" ::: "memory");
    asm volatile("barrier.cluster.wait.aligned;" ::: "memory");
}

// ---------------- K3: outcome_pre + hs copy-out ----------------
__global__ void k3_outcome(const float* __restrict__ w_fc, const float* __restrict__ b_fc,
                           const float* __restrict__ hs_src, float* __restrict__ pre) {
    __shared__ float swfc[H];
    for (int i = threadIdx.x; i < H; i += blockDim.x) swfc[i] = w_fc[i];
    __syncthreads();
    int lane = threadIdx.x & 31;
    int wid  = threadIdx.x >> 5;
    int wpb  = blockDim.x >> 5;
    float bf = b_fc[0];
    for (int t = blockIdx.x * wpb + wid; t < T_STEPS; t += gridDim.x * wpb) {
        const float* hrow = hs_src + t * H;
        float acc = 0.f;
        for (int i = lane; i < H; i += 32) acc = fmaf(hrow[i], swfc[i], acc);
        #pragma unroll
        for (int o = 16; o > 0; o >>= 1) acc += __shfl_xor_sync(0xffffffffu, acc, o);
        if (lane == 0) pre[t] = acc + bf;
    }
}

__global__ void k3_copy(float* __restrict__ dst) {
    const float4* src = reinterpret_cast<const float4*>(g_hs);
    float4* d = reinterpret_cast<float4*>(dst);
    int n4 = T_STEPS * H / 4;
    for (int i = blockIdx.x * blockDim.x + threadIdx.x; i < n4; i += gridDim.x * blockDim.x)
        d[i] = src[i];
}

// ---------------- launch ----------------
extern "C" void kernel_launch(void* const* d_in, const int* in_sizes, int n_in,
                              void* d_out, int out_size) {
    const float* angle  = (const float*)d_in[0];
    const float* rule   = (const float*)d_in[1];
    const float* w_rule = (const float*)d_in[2];
    const float* b_rule = (const float*)d_in[3];
    const float* w_ih   = (const float*)d_in[4];
    const float* w_hh   = (const float*)d_in[5];
    const float* b_ih   = (const float*)d_in[6];
    const float* b_hh   = (const float*)d_in[7];
    const float* w_fc   = (const float*)d_in[8];
    const float* b_fc   = (const float*)d_in[9];
    float* out = (float*)d_out;

    // Output layout resolution
    float* pre = nullptr;
    float* hs_dst = nullptr;
    if (out_size == T_STEPS * (H + 1)) { pre = out; hs_dst = out + T_STEPS; }
    else if (out_size == T_STEPS * H)  { hs_dst = out; }
    else if (out_size == T_STEPS)      { pre = out; }
    else {
        pre = out;
        if (out_size >= T_STEPS * (H + 1)) hs_dst = out + (out_size - T_STEPS * H);
    }

    k0_prep<<<(H + 255) / 256, 256>>>(w_rule, b_rule, w_ih, b_ih, b_hh);
    k0_transpose<<<(H * H + 255) / 256, 256>>>(w_ih);
    k1_xw<<<T_STEPS / TT, 384>>>(angle, rule);

    // k2 writes hidden states directly into the output buffer when possible
    float* hs_target;
    cudaGetSymbolAddress((void**)&hs_target, g_hs);
    float* hs_store = hs_dst ? hs_dst : hs_target;

    // 12-CTA nonportable cluster launch
    cudaFuncSetAttribute(k2_rnn, cudaFuncAttributeNonPortableClusterSizeAllowed, 1);
    {
        cudaLaunchConfig_t cfg = {};
        cfg.gridDim  = dim3(CSZ, 1, 1);
        cfg.blockDim = dim3(NTHR, 1, 1);
        cfg.dynamicSmemBytes = 0;
        cfg.stream = 0;
        cudaLaunchAttribute attrs[1];
        attrs[0].id = cudaLaunchAttributeClusterDimension;
        attrs[0].val.clusterDim.x = CSZ;
        attrs[0].val.clusterDim.y = 1;
        attrs[0].val.clusterDim.z = 1;
        cfg.attrs = attrs;
        cfg.numAttrs = 1;
        cudaLaunchKernelEx(&cfg, k2_rnn, w_hh, hs_store);
    }

    if (pre) k3_outcome<<<256, 256>>>(w_fc, b_fc, hs_store, pre);
}

// round 15
// speedup vs baseline: 1.0022x; 1.0022x over previous
#include <cuda_runtime.h>

#define T_STEPS 16384
#define H 361

#define CSZ 12             /* cluster CTAs == sources == segments */
#define RPC 32             /* rows per CTA (lane l <-> row rank*32+l) */
#define SEGC 32            /* columns per segment */
#define HB 384             /* h buffer floats */
#define NTHR 384           /* 12 warps: warp s consumes source s, sends to CTA s */
#define TXB 128            /* 32 lanes x 4B per (source, consumer, step) */
#define PSTR 33            /* psum row stride (conflict-free) */

#define KAPPA_F 32.84045313f
#define NORMF   2.2773755f
#define DEG2RAD 0.017453292519943295f
#define SC2LOG2E 2.885390081777927f   /* 2*log2(e): pre-scale so sum feeds ex2 */

// ---------------- device scratch ----------------
__device__ float g_xw[T_STEPS * H];     // stores 2*log2(e) * xw
__device__ float g_W2T[H * 368];
__device__ float g_A[H];
__device__ float g_C[H];
__device__ float g_hs[T_STEPS * H];

__device__ __forceinline__ unsigned smem_u32(const void* p) {
    return (unsigned)__cvta_generic_to_shared(p);
}
__device__ __forceinline__ unsigned mapa_u32(unsigned addr, unsigned rank) {
    unsigned r;
    asm("mapa.shared::cluster.u32 %0, %1, %2;" : "=r"(r) : "r"(addr), "r"(rank));
    return r;
}

// ---------------- K0: collapse rule projection + biases ----------------
__global__ void k0_prep(const float* __restrict__ w_rule, const float* __restrict__ b_rule,
                        const float* __restrict__ w_ih, const float* __restrict__ b_ih,
                        const float* __restrict__ b_hh) {
    int j = blockIdx.x * blockDim.x + threadIdx.x;
    if (j >= H) return;
    float a = 0.f, c = 0.f;
    const float* wr = w_ih + j * 489;
    for (int k = 0; k < 128; k++) {
        float w = wr[k];
        a = fmaf(w_rule[k], w, a);
        c = fmaf(b_rule[k], w, c);
    }
    g_A[j] = a;
    g_C[j] = c + b_ih[j] + b_hh[j];
}

__global__ void k0_transpose(const float* __restrict__ w_ih) {
    int idx = blockIdx.x * blockDim.x + threadIdx.x;
    if (idx >= H * H) return;
    int j = idx / H;
    int g = idx - j * H;
    g_W2T[g * 368 + j] = w_ih[j * 489 + 128 + g];
}

// ---------------- K1: xw precompute (pre-scaled by 2*log2e) ----------------
// R15: __cosf (MUFU) instead of software cosf; TT=32 halves W2T L2 traffic.
#define TT 32
__global__ __launch_bounds__(384) void k1_xw(const float* __restrict__ angle,
                                             const float* __restrict__ rule) {
    __shared__ float sE[TT][H];
    __shared__ float sAng[TT], sRule[TT];
    int tid = threadIdx.x;
    int t0 = blockIdx.x * TT;
    if (tid < TT) {
        sAng[tid]  = angle[t0 + tid] * DEG2RAD;
        sRule[tid] = rule[t0 + tid];
    }
    __syncthreads();
    if (tid < H) {
        float gr = (float)tid * DEG2RAD;
        #pragma unroll
        for (int tt = 0; tt < TT; tt++) {
            float th = gr - sAng[tt];
            sE[tt][tid] = __expf(KAPPA_F * (__cosf(th) - 1.0f)) * NORMF;
        }
    }
    __syncthreads();
    if (tid < H) {
        float acc[TT];
        #pragma unroll
        for (int tt = 0; tt < TT; tt++) acc[tt] = 0.f;
        #pragma unroll 2
        for (int g = 0; g < H; g++) {
            float w = g_W2T[g * 368 + tid];
            #pragma unroll
            for (int tt = 0; tt < TT; tt++) acc[tt] = fmaf(sE[tt][g], w, acc[tt]);
        }
        float aj = g_A[tid], cj = g_C[tid];
        #pragma unroll
        for (int tt = 0; tt < TT; tt++)
            g_xw[(t0 + tt) * H + tid] = (acc[tt] + fmaf(sRule[tt], aj, cj)) * SC2LOG2E;
    }
}

// ---------------- K2: warp-per-source RNN, 12-CTA cluster (frozen at R12) ----------------
__global__ void __launch_bounds__(NTHR, 1)
k2_rnn(const float* __restrict__ w_hh) {
    __shared__ __align__(16) float hbuf0[HB];
    __shared__ __align__(16) float hbuf1[HB];
    __shared__ float psum[CSZ * PSTR];
    __shared__ __align__(8) unsigned long long mbar[2][CSZ];

    int tid  = threadIdx.x;
    int lane = tid & 31;
    int s    = tid >> 5;          // warp id == source id == send-dest CTA id
    unsigned rank;
    asm("mov.u32 %0, %%cluster_ctarank;" : "=r"(rank));
    int grow = (int)rank * RPC + lane;   // the row this lane serves
    bool rowok = (grow < H);

    for (int i = tid; i < HB; i += NTHR) { hbuf0[i] = 0.f; hbuf1[i] = 0.f; }
    if (tid == 0) {
        for (int b = 0; b < 2; b++)
            for (int k = 0; k < CSZ; k++) {
                unsigned mb = smem_u32(&mbar[b][k]);
                asm volatile("mbarrier.init.shared.b64 [%0], 1;" :: "r"(mb) : "memory");
                asm volatile("mbarrier.arrive.expect_tx.shared.b64 _, [%0], %1;"
                             :: "r"(mb), "r"((unsigned)TXB) : "memory");
            }
    }

    // weights: lane l of warp s holds 2log2e * W[grow, 32s..32s+32) as 16 f32x2
    unsigned long long wp[SEGC / 2];
    #pragma unroll
    for (int i = 0; i < SEGC / 2; i++) {
        int c0 = s * SEGC + 2 * i;
        int c1 = c0 + 1;
        float a = (rowok && c0 < H) ? w_hh[grow * H + c0] * SC2LOG2E : 0.f;
        float b = (rowok && c1 < H) ? w_hh[grow * H + c1] * SC2LOG2E : 0.f;
        asm("mov.b64 %0, {%1, %2};" : "=l"(wp[i]) : "f"(a), "f"(b));
    }

    unsigned mbA = smem_u32(&mbar[0][s]);   // my wait barriers (source s)
    unsigned mbB = smem_u32(&mbar[1][s]);
    // my send endpoint: warp s delivers this CTA's 32 h values to CTA s
    unsigned sd0 = 0, sd1 = 0, sm0 = 0, sm1 = 0;
    {
        unsigned off = (unsigned)(rank * RPC + lane) * 4u;
        sd0 = mapa_u32(smem_u32(hbuf0) + off, (unsigned)s);
        sd1 = mapa_u32(smem_u32(hbuf1) + off, (unsigned)s);
        sm0 = mapa_u32(smem_u32(&mbar[0][rank]), (unsigned)s);
        sm1 = mapa_u32(smem_u32(&mbar[1][rank]), (unsigned)s);
    }

    float xw_cur = (s == 0 && rowok) ? g_xw[grow] : 0.f;
    unsigned pA = 0, pB = 0;

    __syncthreads();
    asm volatile("barrier.cluster.arrive.aligned;" ::: "memory");
    asm volatile("barrier.cluster.wait.aligned;" ::: "memory");

    for (int t = 0; t < T_STEPS; t++) {
        const float* cur = (t & 1) ? hbuf1 : hbuf0;
        unsigned mb = (t & 1) ? mbB : mbA;

        if (t) {
            unsigned par = (t & 1) ? pB : pA;
            // all lanes wait (warp-synchronous poll)
            asm volatile(
                "{\n\t.reg .pred P1;\n\t"
                "WAITLP_%=:\n\t"
                "mbarrier.try_wait.parity.acquire.cluster.shared::cta.b64 P1, [%0], %1, 0x989680;\n\t"
                "@!P1 bra WAITLP_%=;\n\t}"
                :: "r"(mb), "r"(par) : "memory");
            if (t & 1) pB ^= 1; else pA ^= 1;
        }

        // segment dot: 8 broadcast 16B LDS + 16 f32x2 FMAs (2 chains)
        const double2* h2 = reinterpret_cast<const double2*>(cur + s * SEGC);
        unsigned long long a01 = 0ull, a23 = 0ull;
        #pragma unroll
        for (int i = 0; i < 8; i++) {
            double2 hv = h2[i];
            unsigned long long hlo = __double_as_longlong(hv.x);
            unsigned long long hhi = __double_as_longlong(hv.y);
            asm("fma.rn.f32x2 %0, %1, %2, %0;" : "+l"(a01) : "l"(wp[2 * i]),     "l"(hlo));
            asm("fma.rn.f32x2 %0, %1, %2, %0;" : "+l"(a23) : "l"(wp[2 * i + 1]), "l"(hhi));
        }
        unsigned long long ssum;
        asm("add.rn.f32x2 %0, %1, %2;" : "=l"(ssum) : "l"(a01), "l"(a23));
        unsigned alo, ahi;
        asm("mov.b64 {%0, %1}, %2;" : "=r"(alo), "=r"(ahi) : "l"(ssum));
        float part = __uint_as_float(alo) + __uint_as_float(ahi);
        if (s == 0) part += xw_cur;            // fold (pre-scaled) input drive
        psum[s * PSTR + lane] = part;

        // prefetch next xw while others finish (warp 0 only)
        float xw_nxt = 0.f;
        if (s == 0 && rowok && (t + 1 < T_STEPS)) xw_nxt = __ldg(&g_xw[(t + 1) * H + grow]);

        __syncthreads();   // all 12 partials staged; also fences buf reads

        // every warp redundantly: depth-4 tree sum + tanh (parallel across SMSPs)
        float p0  = psum[lane],             p1  = psum[PSTR + lane];
        float p2  = psum[2 * PSTR + lane],  p3  = psum[3 * PSTR + lane];
        float p4  = psum[4 * PSTR + lane],  p5  = psum[5 * PSTR + lane];
        float p6  = psum[6 * PSTR + lane],  p7  = psum[7 * PSTR + lane];
        float p8  = psum[8 * PSTR + lane],  p9  = psum[9 * PSTR + lane];
        float p10 = psum[10 * PSTR + lane], p11 = psum[11 * PSTR + lane];
        float q0 = p0 + p1,  q1 = p2 + p3,  q2 = p4 + p5;
        float q3 = p6 + p7,  q4 = p8 + p9,  q5 = p10 + p11;
        float r0 = q0 + q1,  r1 = q2 + q3,  r2 = q4 + q5;
        float v  = (r0 + r1) + r2;          // = 2*log2e*(W h + xw)

        float e;
        asm("ex2.approx.f32 %0, %1;" : "=f"(e) : "f"(v));   // e^{2x}
        float hval = 1.0f - __fdividef(2.0f, e + 1.0f);     // tanh(x); pads -> 0

        if (s == 1 && rowok) g_hs[t * H + grow] = hval;     // coalesced STG, warp 1

        if (t + 1 < T_STEPS) {
            // warp s: ONE coalesced 128B st.async to CTA s (buf (t+1)&1)
            unsigned d = (t & 1) ? sd0 : sd1;
            unsigned m = (t & 1) ? sm0 : sm1;
            asm volatile(
                "st.async.shared::cluster.mbarrier::complete_tx::bytes.u32 [%0], %1, [%2];"
                :: "r"(d), "r"(__float_as_uint(hval)), "r"(m) : "memory");
        }
        // re-arm the barrier consumed this step, for step t+2 (off critical path;
        // early complete_tx is legal — pending arrive gates phase completion)
        if (t && lane == 0) {
            asm volatile("mbarrier.arrive.expect_tx.shared.b64 _, [%0], %1;"
                         :: "r"(mb), "r"((unsigned)TXB) : "memory");
        }
        xw_cur = xw_nxt;
    }
    asm volatile("barrier.cluster.arrive.aligned;" ::: "memory");
    asm volatile("barrier.cluster.wait.aligned;" ::: "memory");
}

// ---------------- K3: outcome_pre + hs copy-out ----------------
__global__ void k3_outcome(const float* __restrict__ w_fc, const float* __restrict__ b_fc,
                           float* __restrict__ pre) {
    __shared__ float swfc[H];
    for (int i = threadIdx.x; i < H; i += blockDim.x) swfc[i] = w_fc[i];
    __syncthreads();
    int lane = threadIdx.x & 31;
    int wid  = threadIdx.x >> 5;
    int wpb  = blockDim.x >> 5;
    float bf = b_fc[0];
    for (int t = blockIdx.x * wpb + wid; t < T_STEPS; t += gridDim.x * wpb) {
        const float* hrow = g_hs + t * H;
        float acc = 0.f;
        for (int i = lane; i < H; i += 32) acc = fmaf(hrow[i], swfc[i], acc);
        #pragma unroll
        for (int o = 16; o > 0; o >>= 1) acc += __shfl_xor_sync(0xffffffffu, acc, o);
        if (lane == 0) pre[t] = acc + bf;
    }
}

__global__ void k3_copy(float* __restrict__ dst) {
    const float4* src = reinterpret_cast<const float4*>(g_hs);
    float4* d = reinterpret_cast<float4*>(dst);
    int n4 = T_STEPS * H / 4;
    for (int i = blockIdx.x * blockDim.x + threadIdx.x; i < n4; i += gridDim.x * blockDim.x)
        d[i] = src[i];
}

// ---------------- launch ----------------
extern "C" void kernel_launch(void* const* d_in, const int* in_sizes, int n_in,
                              void* d_out, int out_size) {
    const float* angle  = (const float*)d_in[0];
    const float* rule   = (const float*)d_in[1];
    const float* w_rule = (const float*)d_in[2];
    const float* b_rule = (const float*)d_in[3];
    const float* w_ih   = (const float*)d_in[4];
    const float* w_hh   = (const float*)d_in[5];
    const float* b_ih   = (const float*)d_in[6];
    const float* b_hh   = (const float*)d_in[7];
    const float* w_fc   = (const float*)d_in[8];
    const float* b_fc   = (const float*)d_in[9];
    float* out = (float*)d_out;

    k0_prep<<<(H + 255) / 256, 256>>>(w_rule, b_rule, w_ih, b_ih, b_hh);
    k0_transpose<<<(H * H + 255) / 256, 256>>>(w_ih);
    k1_xw<<<T_STEPS / TT, 384>>>(angle, rule);

    // 12-CTA nonportable cluster launch
    cudaFuncSetAttribute(k2_rnn, cudaFuncAttributeNonPortableClusterSizeAllowed, 1);
    {
        cudaLaunchConfig_t cfg = {};
        cfg.gridDim  = dim3(CSZ, 1, 1);
        cfg.blockDim = dim3(NTHR, 1, 1);
        cfg.dynamicSmemBytes = 0;
        cfg.stream = 0;
        cudaLaunchAttribute attrs[1];
        attrs[0].id = cudaLaunchAttributeClusterDimension;
        attrs[0].val.clusterDim.x = CSZ;
        attrs[0].val.clusterDim.y = 1;
        attrs[0].val.clusterDim.z = 1;
        cfg.attrs = attrs;
        cfg.numAttrs = 1;
        cudaLaunchKernelEx(&cfg, k2_rnn, w_hh);
    }

    float* pre = nullptr;
    float* hs_dst = nullptr;
    if (out_size == T_STEPS * (H + 1)) { pre = out; hs_dst = out + T_STEPS; }
    else if (out_size == T_STEPS * H)  { hs_dst = out; }
    else if (out_size == T_STEPS)      { pre = out; }
    else {
        pre = out;
        if (out_size >= T_STEPS * (H + 1)) hs_dst = out + (out_size - T_STEPS * H);
    }
    if (hs_dst) k3_copy<<<1024, 256>>>(hs_dst);
    if (pre)    k3_outcome<<<256, 256>>>(w_fc, b_fc, pre);
}

// round 17
// speedup vs baseline: 1.0122x; 1.0100x over previous
#include <cuda_runtime.h>

#define T_STEPS 16384
#define H 361

#define CSZ 12             /* cluster CTAs == sources == segments */
#define RPC 32             /* rows per CTA (lane l <-> row rank*32+l) */
#define SEGC 32            /* columns per segment */
#define HB 384             /* h buffer floats */
#define NTHR 384           /* 12 warps: warp s consumes source s, sends to CTA s */
#define TXB 128            /* 32 lanes x 4B per (source, consumer, step) */
#define PSTR 33            /* psum row stride (conflict-free) */

#define KAPPA_F 32.84045313f
#define NORMF   2.2773755f
#define DEG2RAD 0.017453292519943295f
#define SC2LOG2E 2.885390081777927f   /* 2*log2(e): pre-scale so sum feeds ex2 */

// ---------------- device scratch ----------------
__device__ float g_xw[T_STEPS * H];     // stores 2*log2(e) * xw
__device__ float g_W2T[H * 368];
__device__ float g_A[H];
__device__ float g_C[H];
__device__ float g_hs[T_STEPS * H];

__device__ __forceinline__ unsigned smem_u32(const void* p) {
    return (unsigned)__cvta_generic_to_shared(p);
}
__device__ __forceinline__ unsigned mapa_u32(unsigned addr, unsigned rank) {
    unsigned r;
    asm("mapa.shared::cluster.u32 %0, %1, %2;" : "=r"(r) : "r"(addr), "r"(rank));
    return r;
}

// ---------------- K0: collapse rule projection + biases ----------------
__global__ void k0_prep(const float* __restrict__ w_rule, const float* __restrict__ b_rule,
                        const float* __restrict__ w_ih, const float* __restrict__ b_ih,
                        const float* __restrict__ b_hh) {
    int j = blockIdx.x * blockDim.x + threadIdx.x;
    if (j >= H) return;
    float a = 0.f, c = 0.f;
    const float* wr = w_ih + j * 489;
    for (int k = 0; k < 128; k++) {
        float w = wr[k];
        a = fmaf(w_rule[k], w, a);
        c = fmaf(b_rule[k], w, c);
    }
    g_A[j] = a;
    g_C[j] = c + b_ih[j] + b_hh[j];
}

__global__ void k0_transpose(const float* __restrict__ w_ih) {
    int idx = blockIdx.x * blockDim.x + threadIdx.x;
    if (idx >= H * H) return;
    int j = idx / H;
    int g = idx - j * H;
    g_W2T[g * 368 + j] = w_ih[j * 489 + 128 + g];
}

// ---------------- K1: xw precompute (output pre-scaled by 2*log2e) ----------------
#define TT 16
__global__ __launch_bounds__(384) void k1_xw(const float* __restrict__ angle,
                                             const float* __restrict__ rule) {
    __shared__ float sE[TT][H];
    __shared__ float sAng[TT], sRule[TT];
    int tid = threadIdx.x;
    int t0 = blockIdx.x * TT;
    if (tid < TT) {
        sAng[tid]  = angle[t0 + tid] * DEG2RAD;
        sRule[tid] = rule[t0 + tid];
    }
    __syncthreads();
    if (tid < H) {
        float gr = (float)tid * DEG2RAD;
        #pragma unroll
        for (int tt = 0; tt < TT; tt++) {
            float th = gr - sAng[tt];
            sE[tt][tid] = __expf(KAPPA_F * (cosf(th) - 1.0f)) * NORMF;
        }
    }
    __syncthreads();
    if (tid < H) {
        float acc[TT];
        #pragma unroll
        for (int tt = 0; tt < TT; tt++) acc[tt] = 0.f;
        #pragma unroll 2
        for (int g = 0; g < H; g++) {
            float w = g_W2T[g * 368 + tid];
            #pragma unroll
            for (int tt = 0; tt < TT; tt++) acc[tt] = fmaf(sE[tt][g], w, acc[tt]);
        }
        float aj = g_A[tid], cj = g_C[tid];
        #pragma unroll
        for (int tt = 0; tt < TT; tt++)
            g_xw[(t0 + tt) * H + tid] = (acc[tt] + fmaf(sRule[tt], aj, cj)) * SC2LOG2E;
    }
}

// ---------------- K2: warp-per-source RNN, 12-CTA cluster, distributed sends ----------------
// Best-measured configuration (R12): per-source mbarriers; all-lane try_wait;
// weights/xw pre-scaled by 2*log2e (sum feeds ex2 directly); depth-4 tree sum;
// re-arm after wait; one coalesced 128B st.async per warp (data + tx-signal).
__global__ void __launch_bounds__(NTHR, 1)
k2_rnn(const float* __restrict__ w_hh) {
    __shared__ __align__(16) float hbuf0[HB];
    __shared__ __align__(16) float hbuf1[HB];
    __shared__ float psum[CSZ * PSTR];
    __shared__ __align__(8) unsigned long long mbar[2][CSZ];

    int tid  = threadIdx.x;
    int lane = tid & 31;
    int s    = tid >> 5;          // warp id == source id == send-dest CTA id
    unsigned rank;
    asm("mov.u32 %0, %%cluster_ctarank;" : "=r"(rank));
    int grow = (int)rank * RPC + lane;   // the row this lane serves
    bool rowok = (grow < H);

    for (int i = tid; i < HB; i += NTHR) { hbuf0[i] = 0.f; hbuf1[i] = 0.f; }
    if (tid == 0) {
        for (int b = 0; b < 2; b++)
            for (int k = 0; k < CSZ; k++) {
                unsigned mb = smem_u32(&mbar[b][k]);
                asm volatile("mbarrier.init.shared.b64 [%0], 1;" :: "r"(mb) : "memory");
                asm volatile("mbarrier.arrive.expect_tx.shared.b64 _, [%0], %1;"
                             :: "r"(mb), "r"((unsigned)TXB) : "memory");
            }
    }

    // weights: lane l of warp s holds 2log2e * W[grow, 32s..32s+32) as 16 f32x2
    unsigned long long wp[SEGC / 2];
    #pragma unroll
    for (int i = 0; i < SEGC / 2; i++) {
        int c0 = s * SEGC + 2 * i;
        int c1 = c0 + 1;
        float a = (rowok && c0 < H) ? w_hh[grow * H + c0] * SC2LOG2E : 0.f;
        float b = (rowok && c1 < H) ? w_hh[grow * H + c1] * SC2LOG2E : 0.f;
        asm("mov.b64 %0, {%1, %2};" : "=l"(wp[i]) : "f"(a), "f"(b));
    }

    unsigned mbA = smem_u32(&mbar[0][s]);   // my wait barriers (source s)
    unsigned mbB = smem_u32(&mbar[1][s]);
    // my send endpoint: warp s delivers this CTA's 32 h values to CTA s
    unsigned sd0 = 0, sd1 = 0, sm0 = 0, sm1 = 0;
    {
        unsigned off = (unsigned)(rank * RPC + lane) * 4u;
        sd0 = mapa_u32(smem_u32(hbuf0) + off, (unsigned)s);
        sd1 = mapa_u32(smem_u32(hbuf1) + off, (unsigned)s);
        sm0 = mapa_u32(smem_u32(&mbar[0][rank]), (unsigned)s);
        sm1 = mapa_u32(smem_u32(&mbar[1][rank]), (unsigned)s);
    }

    float xw_cur = (s == 0 && rowok) ? g_xw[grow] : 0.f;
    unsigned pA = 0, pB = 0;

    __syncthreads();
    asm volatile("barrier.cluster.arrive.aligned;" ::: "memory");
    asm volatile("barrier.cluster.wait.aligned;" ::: "memory");

    for (int t = 0; t < T_STEPS; t++) {
        const float* cur = (t & 1) ? hbuf1 : hbuf0;
        unsigned mb = (t & 1) ? mbB : mbA;

        if (t) {
            unsigned par = (t & 1) ? pB : pA;
            // all lanes wait (warp-synchronous poll)
            asm volatile(
                "{\n\t.reg .pred P1;\n\t"
                "WAITLP_%=:\n\t"
                "mbarrier.try_wait.parity.acquire.cluster.shared::cta.b64 P1, [%0], %1, 0x989680;\n\t"
                "@!P1 bra WAITLP_%=;\n\t}"
                :: "r"(mb), "r"(par) : "memory");
            if (t & 1) pB ^= 1; else pA ^= 1;
        }

        // segment dot: 8 broadcast 16B LDS + 16 f32x2 FMAs (2 chains)
        const double2* h2 = reinterpret_cast<const double2*>(cur + s * SEGC);
        unsigned long long a01 = 0ull, a23 = 0ull;
        #pragma unroll
        for (int i = 0; i < 8; i++) {
            double2 hv = h2[i];
            unsigned long long hlo = __double_as_longlong(hv.x);
            unsigned long long hhi = __double_as_longlong(hv.y);
            asm("fma.rn.f32x2 %0, %1, %2, %0;" : "+l"(a01) : "l"(wp[2 * i]),     "l"(hlo));
            asm("fma.rn.f32x2 %0, %1, %2, %0;" : "+l"(a23) : "l"(wp[2 * i + 1]), "l"(hhi));
        }
        unsigned long long ssum;
        asm("add.rn.f32x2 %0, %1, %2;" : "=l"(ssum) : "l"(a01), "l"(a23));
        unsigned alo, ahi;
        asm("mov.b64 {%0, %1}, %2;" : "=r"(alo), "=r"(ahi) : "l"(ssum));
        float part = __uint_as_float(alo) + __uint_as_float(ahi);
        if (s == 0) part += xw_cur;            // fold (pre-scaled) input drive
        psum[s * PSTR + lane] = part;

        // prefetch next xw while others finish (warp 0 only)
        float xw_nxt = 0.f;
        if (s == 0 && rowok && (t + 1 < T_STEPS)) xw_nxt = __ldg(&g_xw[(t + 1) * H + grow]);

        __syncthreads();   // all 12 partials staged; also fences buf reads

        // every warp redundantly: depth-4 tree sum + tanh (parallel across SMSPs)
        float p0  = psum[lane],             p1  = psum[PSTR + lane];
        float p2  = psum[2 * PSTR + lane],  p3  = psum[3 * PSTR + lane];
        float p4  = psum[4 * PSTR + lane],  p5  = psum[5 * PSTR + lane];
        float p6  = psum[6 * PSTR + lane],  p7  = psum[7 * PSTR + lane];
        float p8  = psum[8 * PSTR + lane],  p9  = psum[9 * PSTR + lane];
        float p10 = psum[10 * PSTR + lane], p11 = psum[11 * PSTR + lane];
        float q0 = p0 + p1,  q1 = p2 + p3,  q2 = p4 + p5;
        float q3 = p6 + p7,  q4 = p8 + p9,  q5 = p10 + p11;
        float r0 = q0 + q1,  r1 = q2 + q3,  r2 = q4 + q5;
        float v  = (r0 + r1) + r2;          // = 2*log2e*(W h + xw)

        float e;
        asm("ex2.approx.f32 %0, %1;" : "=f"(e) : "f"(v));   // e^{2x}
        float hval = 1.0f - __fdividef(2.0f, e + 1.0f);     // tanh(x); pads -> 0

        if (s == 1 && rowok) g_hs[t * H + grow] = hval;     // coalesced STG, warp 1

        if (t + 1 < T_STEPS) {
            // warp s: ONE coalesced 128B st.async to CTA s (buf (t+1)&1)
            unsigned d = (t & 1) ? sd0 : sd1;
            unsigned m = (t & 1) ? sm0 : sm1;
            asm volatile(
                "st.async.shared::cluster.mbarrier::complete_tx::bytes.u32 [%0], %1, [%2];"
                :: "r"(d), "r"(__float_as_uint(hval)), "r"(m) : "memory");
        }
        // re-arm the barrier consumed this step, for step t+2 (off critical path;
        // early complete_tx is legal — pending arrive gates phase completion)
        if (t && lane == 0) {
            asm volatile("mbarrier.arrive.expect_tx.shared.b64 _, [%0], %1;"
                         :: "r"(mb), "r"((unsigned)TXB) : "memory");
        }
        xw_cur = xw_nxt;
    }
    asm volatile("barrier.cluster.arrive.aligned;" ::: "memory");
    asm volatile("barrier.cluster.wait.aligned;" ::: "memory");
}

// ---------------- K3: outcome_pre + hs copy-out ----------------
__global__ void k3_outcome(const float* __restrict__ w_fc, const float* __restrict__ b_fc,
                           float* __restrict__ pre) {
    __shared__ float swfc[H];
    for (int i = threadIdx.x; i < H; i += blockDim.x) swfc[i] = w_fc[i];
    __syncthreads();
    int lane = threadIdx.x & 31;
    int wid  = threadIdx.x >> 5;
    int wpb  = blockDim.x >> 5;
    float bf = b_fc[0];
    for (int t = blockIdx.x * wpb + wid; t < T_STEPS; t += gridDim.x * wpb) {
        const float* hrow = g_hs + t * H;
        float acc = 0.f;
        for (int i = lane; i < H; i += 32) acc = fmaf(hrow[i], swfc[i], acc);
        #pragma unroll
        for (int o = 16; o > 0; o >>= 1) acc += __shfl_xor_sync(0xffffffffu, acc, o);
        if (lane == 0) pre[t] = acc + bf;
    }
}

__global__ void k3_copy(float* __restrict__ dst) {
    const float4* src = reinterpret_cast<const float4*>(g_hs);
    float4* d = reinterpret_cast<float4*>(dst);
    int n4 = T_STEPS * H / 4;
    for (int i = blockIdx.x * blockDim.x + threadIdx.x; i < n4; i += gridDim.x * blockDim.x)
        d[i] = src[i];
}

// ---------------- launch ----------------
extern "C" void kernel_launch(void* const* d_in, const int* in_sizes, int n_in,
                              void* d_out, int out_size) {
    const float* angle  = (const float*)d_in[0];
    const float* rule   = (const float*)d_in[1];
    const float* w_rule = (const float*)d_in[2];
    const float* b_rule = (const float*)d_in[3];
    const float* w_ih   = (const float*)d_in[4];
    const float* w_hh   = (const float*)d_in[5];
    const float* b_ih   = (const float*)d_in[6];
    const float* b_hh   = (const float*)d_in[7];
    const float* w_fc   = (const float*)d_in[8];
    const float* b_fc   = (const float*)d_in[9];
    float* out = (float*)d_out;

    k0_prep<<<(H + 255) / 256, 256>>>(w_rule, b_rule, w_ih, b_ih, b_hh);
    k0_transpose<<<(H * H + 255) / 256, 256>>>(w_ih);
    k1_xw<<<T_STEPS / TT, 384>>>(angle, rule);

    // 12-CTA nonportable cluster launch
    cudaFuncSetAttribute(k2_rnn, cudaFuncAttributeNonPortableClusterSizeAllowed, 1);
    {
        cudaLaunchConfig_t cfg = {};
        cfg.gridDim  = dim3(CSZ, 1, 1);
        cfg.blockDim = dim3(NTHR, 1, 1);
        cfg.dynamicSmemBytes = 0;
        cfg.stream = 0;
        cudaLaunchAttribute attrs[1];
        attrs[0].id = cudaLaunchAttributeClusterDimension;
        attrs[0].val.clusterDim.x = CSZ;
        attrs[0].val.clusterDim.y = 1;
        attrs[0].val.clusterDim.z = 1;
        cfg.attrs = attrs;
        cfg.numAttrs = 1;
        cudaLaunchKernelEx(&cfg, k2_rnn, w_hh);
    }

    float* pre = nullptr;
    float* hs_dst = nullptr;
    if (out_size == T_STEPS * (H + 1)) { pre = out; hs_dst = out + T_STEPS; }
    else if (out_size == T_STEPS * H)  { hs_dst = out; }
    else if (out_size == T_STEPS)      { pre = out; }
    else {
        pre = out;
        if (out_size >= T_STEPS * (H + 1)) hs_dst = out + (out_size - T_STEPS * H);
    }
    if (hs_dst) k3_copy<<<1024, 256>>>(hs_dst);
    if (pre)    k3_outcome<<<256, 256>>>(w_fc, b_fc, pre);
}